// round 9
// baseline (speedup 1.0000x reference)
#include <cuda_runtime.h>
#include <cuda_fp16.h>
#include <cstdint>
#include <cstddef>

// ============================================================================
// out1[b,h] = sum_i a_h[b,i] * (G @ W1_i)[b,h],  G[b,jk] = v_h[b,j]*t_h[b,k]
// GEMM via mma.sync.m16n8k16 (f16 in, f32 accum).
// CTA: 64 rows x 128 cols (2 i-values), K=4288 in 67 double-buffered stages.
// grid (8, 33) = 264 CTAs -> 2 CTAs/SM.  Partials scaled by a_h at writeout.
// Reduction over i: stage-1 (5 groups of 13) then MLP epilogue.
// ============================================================================

#define DL 64
#define DH 65
#define HID 64
#define BATCH 512
#define KREAL 4225          // 65*65 per i
#define KPAD 4288           // 67 chunks of 64
#define NC 67
#define STAGE_BYTES 24576   // A 8KB + B 16KB
#define GEMM_SMEM (2 * STAGE_BYTES)
#define NGRP 5              // i-reduction groups (5 x 13 = 65)

__device__ __half g_G[(size_t)BATCH * KPAD];              // 4.4 MB
__device__ __half g_Bp[(size_t)DH * HID * KPAD];          // 35.7 MB  [i][h][k]
__device__ float  g_partials[(size_t)BATCH * DH * HID];   // 8.5 MB   [b][i][h]
__device__ float  g_red[(size_t)NGRP * BATCH * HID];      // 0.65 MB  [grp][b][h]

// ---- helpers ---------------------------------------------------------------
static __device__ __forceinline__ uint32_t smem_u32(const void* p) {
    uint32_t a;
    asm("{ .reg .u64 t; cvta.to.shared.u64 t, %1; cvt.u32.u64 %0, t; }"
        : "=r"(a) : "l"(p));
    return a;
}
static __device__ __forceinline__ void cp16(uint32_t dst, const void* src) {
    asm volatile("cp.async.cg.shared.global [%0], [%1], 16;" :: "r"(dst), "l"(src));
}
#define CP_COMMIT() asm volatile("cp.async.commit_group;" ::: "memory")
#define CP_WAIT1()  asm volatile("cp.async.wait_group 1;" ::: "memory")

static __device__ __forceinline__ void ldm_x4(uint32_t* r, uint32_t addr) {
    asm volatile("ldmatrix.sync.aligned.m8n8.x4.shared.b16 {%0,%1,%2,%3}, [%4];"
                 : "=r"(r[0]), "=r"(r[1]), "=r"(r[2]), "=r"(r[3]) : "r"(addr));
}
static __device__ __forceinline__ void mma16816(float* c, const uint32_t* a,
                                                const uint32_t* b) {
    asm volatile(
        "mma.sync.aligned.m16n8k16.row.col.f32.f16.f16.f32 "
        "{%0,%1,%2,%3}, {%4,%5,%6,%7}, {%8,%9}, {%0,%1,%2,%3};"
        : "+f"(c[0]), "+f"(c[1]), "+f"(c[2]), "+f"(c[3])
        : "r"(a[0]), "r"(a[1]), "r"(a[2]), "r"(a[3]), "r"(b[0]), "r"(b[1]));
}

// ============================================================================
// Kernel A: convert+transpose W1 -> Bp[i][h][k] f16, zero-padded to KPAD.
// ============================================================================
__global__ void convert_w1_kernel(const float* __restrict__ W1) {
    __shared__ float ts[64][65];
    const int c = blockIdx.x, i = blockIdx.y;
    const int tid = threadIdx.x;
    for (int e = tid; e < 4096; e += 256) {
        int kl = e >> 6, h = e & 63;
        int jk = c * 64 + kl;
        ts[kl][h] = (jk < KREAL) ? W1[((size_t)i * KREAL + jk) * HID + h] : 0.0f;
    }
    __syncthreads();
    for (int t = tid; t < 512; t += 256) {
        int h = t >> 3, k16 = t & 7;
        uint32_t u[4];
        #pragma unroll
        for (int q = 0; q < 4; ++q) {
            __half2 p = __halves2half2(__float2half_rn(ts[k16 * 8 + 2 * q][h]),
                                       __float2half_rn(ts[k16 * 8 + 2 * q + 1][h]));
            u[q] = *reinterpret_cast<uint32_t*>(&p);
        }
        *reinterpret_cast<uint4*>(&g_Bp[((size_t)i * HID + h) * KPAD + c * 64 + k16 * 8])
            = make_uint4(u[0], u[1], u[2], u[3]);
    }
}

// ============================================================================
// Kernel B: build G[b][jk] = v_h[b,j]*t_h[b,k] f16, zero-padded. grid 512.
// ============================================================================
__global__ void build_g_kernel(const float* __restrict__ l,
                               const float* __restrict__ v) {
    const int b = blockIdx.x;
    const int tid = threadIdx.x;
    __shared__ float vs[DH], tsh[DH];
    if (tid < DH) vs[tid] = (tid == 0) ? 1.0f : v[(size_t)b * DL + tid - 1];
    if (tid >= 128 && tid < 128 + DH)
        tsh[tid - 128] = (tid == 128) ? 1.0f : l[(size_t)b * DL + tid - 129];
    __syncthreads();
    for (int p = tid; p < KPAD / 2; p += 256) {
        int jk0 = 2 * p, jk1 = 2 * p + 1;
        float f0 = (jk0 < KREAL) ? vs[jk0 / DH] * tsh[jk0 % DH] : 0.0f;
        float f1 = (jk1 < KREAL) ? vs[jk1 / DH] * tsh[jk1 % DH] : 0.0f;
        __half2 h2 = __halves2half2(__float2half_rn(f0), __float2half_rn(f1));
        *reinterpret_cast<uint32_t*>(&g_G[(size_t)b * KPAD + jk0])
            = *reinterpret_cast<uint32_t*>(&h2);
    }
}

// ============================================================================
// Kernel C: main GEMM. grid (8 mtiles, 33 i-pairs), 256 thr, 2 CTAs/SM.
// smem/stage: A[64 rows][64 f16] (8KB) | B[128 n][64 f16] (16KB), swizzled:
//   16B chunk ch (0-7) stored at ch ^ (row & 7).
// Warps: 2m x 4n; warp tile 32m x 32n; acc 2x4 m16n8 frags (32 regs).
// ============================================================================
__global__ void __launch_bounds__(256)
fusion_mma_kernel(const float* __restrict__ a) {
    extern __shared__ char smc[];
    const uint32_t smb = smem_u32(smc);
    const int tid = threadIdx.x;
    const int lane = tid & 31;
    const int warp = tid >> 5;
    const int wm = warp & 1;          // 2 m-warps
    const int wn = warp >> 1;         // 4 n-warps
    const int mt = blockIdx.x, g = blockIdx.y;
    const int b0 = mt * 64;
    const int i0 = g * 2;

    auto issue_loads = [&](int c) {
        if (c >= NC) return;
        const uint32_t Ab = smb + (uint32_t)(c & 1) * STAGE_BYTES;
        const uint32_t Bb = Ab + 8192u;
        #pragma unroll
        for (int w = 0; w < 2; ++w) {                 // A: 64 rows x 8 chunks
            int idx = tid + w * 256;
            int row = idx >> 3, ch = idx & 7;
            cp16(Ab + (uint32_t)(row * 128 + ((ch ^ (row & 7)) << 4)),
                 &g_G[(size_t)(b0 + row) * KPAD + c * 64 + ch * 8]);
        }
        #pragma unroll
        for (int w = 0; w < 4; ++w) {                 // B: 128 n-rows x 8 chunks
            int idx = tid + w * 256;
            int n = idx >> 3, ch = idx & 7;
            int i = i0 + (n >> 6); if (i > DH - 1) i = DH - 1;
            int h = n & 63;
            cp16(Bb + (uint32_t)(n * 128 + ((ch ^ (n & 7)) << 4)),
                 &g_Bp[((size_t)i * HID + h) * KPAD + c * 64 + ch * 8]);
        }
    };

    float acc[2][4][4];
    #pragma unroll
    for (int mi = 0; mi < 2; ++mi)
        #pragma unroll
        for (int nj = 0; nj < 4; ++nj)
            #pragma unroll
            for (int q = 0; q < 4; ++q) acc[mi][nj][q] = 0.0f;

    issue_loads(0); CP_COMMIT();

    for (int c = 0; c < NC; ++c) {
        issue_loads(c + 1); CP_COMMIT();
        CP_WAIT1();                    // stage c resident
        __syncthreads();

        const uint32_t Ab = smb + (uint32_t)(c & 1) * STAGE_BYTES;
        const uint32_t Bb = Ab + 8192u;

        #pragma unroll
        for (int ks = 0; ks < 4; ++ks) {
            uint32_t af[2][4];
            #pragma unroll
            for (int mi = 0; mi < 2; ++mi) {
                int row = wm * 32 + mi * 16 + (lane & 15);
                int ch = 2 * ks + (lane >> 4);
                ldm_x4(af[mi], Ab + (uint32_t)(row * 128 + ((ch ^ (row & 7)) << 4)));
            }
            uint32_t bf[4][2];
            #pragma unroll
            for (int nb = 0; nb < 2; ++nb) {
                int nrow = wn * 32 + nb * 16 + (lane & 7) + ((lane >> 4) << 3);
                int ch = 2 * ks + ((lane >> 3) & 1);
                uint32_t r[4];
                ldm_x4(r, Bb + (uint32_t)(nrow * 128 + ((ch ^ (nrow & 7)) << 4)));
                bf[2 * nb][0] = r[0]; bf[2 * nb][1] = r[1];
                bf[2 * nb + 1][0] = r[2]; bf[2 * nb + 1][1] = r[3];
            }
            #pragma unroll
            for (int mi = 0; mi < 2; ++mi)
                #pragma unroll
                for (int nj = 0; nj < 4; ++nj)
                    mma16816(acc[mi][nj], af[mi], bf[nj]);
        }
        __syncthreads();               // done reading stage c before overwrite
    }

    // ---- writeout: n = wn*32 + nj*8 + (lane&3)*2; i uniform per warp ----
    const int iw = i0 + (wn >> 1);
    if (iw < DH) {
        const int hbase = (wn & 1) * 32;
        #pragma unroll
        for (int mi = 0; mi < 2; ++mi) {
            int bA = b0 + wm * 32 + mi * 16 + (lane >> 2);
            int bB = bA + 8;
            float ahA = (iw == 0) ? 1.0f : __ldg(&a[(size_t)bA * DL + iw - 1]);
            float ahB = (iw == 0) ? 1.0f : __ldg(&a[(size_t)bB * DL + iw - 1]);
            #pragma unroll
            for (int nj = 0; nj < 4; ++nj) {
                int h = hbase + nj * 8 + (lane & 3) * 2;
                float2 vA = make_float2(acc[mi][nj][0] * ahA, acc[mi][nj][1] * ahA);
                float2 vB = make_float2(acc[mi][nj][2] * ahB, acc[mi][nj][3] * ahB);
                *reinterpret_cast<float2*>(
                    &g_partials[((size_t)bA * DH + iw) * HID + h]) = vA;
                *reinterpret_cast<float2*>(
                    &g_partials[((size_t)bB * DH + iw) * HID + h]) = vB;
            }
        }
    }
}

// ============================================================================
// Kernel D1: stage-1 reduction over i: 5 groups of 13. grid 640, 256 thr.
// ============================================================================
__global__ void reduce_partials_kernel() {
    const int idx = blockIdx.x * 256 + threadIdx.x;   // [grp][b][h]
    const int grp = idx >> 15;                        // / 32768
    const int rem = idx & 32767;
    const int b = rem >> 6, h = rem & 63;
    const float* pr = &g_partials[((size_t)b * DH + grp * 13) * HID + h];
    float acc = 0.0f;
    #pragma unroll
    for (int q = 0; q < 13; ++q) acc += pr[(size_t)q * HID];
    g_red[idx] = acc;
}

// ============================================================================
// Kernel D2: reduce 5 groups + bias/tanh + two 64x64 layers. grid 128, 256.
// ============================================================================
__global__ void mlp_epilogue_kernel(const float* __restrict__ b1,
                                    const float* __restrict__ W2,
                                    const float* __restrict__ b2,
                                    const float* __restrict__ W3,
                                    const float* __restrict__ b3,
                                    float* __restrict__ out) {
    const int tid = threadIdx.x;
    const int bl = tid >> 6;
    const int h = tid & 63;
    const int b = blockIdx.x * 4 + bl;
    __shared__ float h1s[4][HID];
    __shared__ float h2s[4][HID];

    float acc = 0.0f;
    #pragma unroll
    for (int grp = 0; grp < NGRP; ++grp)
        acc += g_red[(size_t)grp * BATCH * HID + (size_t)b * HID + h];
    h1s[bl][h] = tanhf(acc + b1[h]);
    __syncthreads();

    float acc2 = b2[h];
    #pragma unroll
    for (int jj = 0; jj < HID; ++jj)
        acc2 = fmaf(h1s[bl][jj], W2[(size_t)jj * HID + h], acc2);
    h2s[bl][h] = tanhf(acc2);
    __syncthreads();

    float acc3 = b3[h];
    #pragma unroll
    for (int jj = 0; jj < HID; ++jj)
        acc3 = fmaf(h2s[bl][jj], W3[(size_t)jj * DL + h], acc3);
    out[(size_t)b * DL + h] = tanhf(acc3);
}

// ============================================================================
extern "C" void kernel_launch(void* const* d_in, const int* in_sizes, int n_in,
                              void* d_out, int out_size) {
    const float* l  = (const float*)d_in[0];
    const float* a  = (const float*)d_in[1];
    const float* v  = (const float*)d_in[2];
    const float* W1 = (const float*)d_in[3];
    const float* b1 = (const float*)d_in[4];
    const float* W2 = (const float*)d_in[5];
    const float* b2 = (const float*)d_in[6];
    const float* W3 = (const float*)d_in[7];
    const float* b3 = (const float*)d_in[8];
    float* out = (float*)d_out;

    cudaFuncSetAttribute(fusion_mma_kernel,
                         cudaFuncAttributeMaxDynamicSharedMemorySize, GEMM_SMEM);

    convert_w1_kernel<<<dim3(NC, DH), 256>>>(W1);
    build_g_kernel<<<BATCH, 256>>>(l, v);
    fusion_mma_kernel<<<dim3(8, 33), 256, GEMM_SMEM>>>(a);
    reduce_partials_kernel<<<640, 256>>>();
    mlp_epilogue_kernel<<<128, 256>>>(b1, W2, b2, W3, b3, out);
}

// round 10
// speedup vs baseline: 1.0394x; 1.0394x over previous
#include <cuda_runtime.h>
#include <cuda_fp16.h>
#include <cstdint>
#include <cstddef>

// ============================================================================
// out1[b,h] = sum_i a_h[b,i] * (G @ W1_i)[b,h],  G[b,jk] = v_h[b,j]*t_h[b,k]
// GEMM via mma.sync.m16n8k16 (f16 in, f32 accum).
// CTA: 128 rows x 128 cols (2 i), K=4288, 3-stage cp.async pipeline,
// ONE __syncthreads per stage. grid (4, 33) = 132 CTAs.
// Epilogue: fused i-reduction + bias/tanh + two 64x64 layers.
// ============================================================================

#define DL 64
#define DH 65
#define HID 64
#define BATCH 512
#define KREAL 4225          // 65*65 per i
#define KPAD 4288           // 67 chunks of 64
#define NC 67
#define PIPE 3
#define STAGE_BYTES 32768   // A 16KB + B 16KB
#define GEMM_SMEM (PIPE * STAGE_BYTES)

__device__ __half g_G[(size_t)BATCH * KPAD];              // 4.4 MB
__device__ __half g_Bp[(size_t)DH * HID * KPAD];          // 35.7 MB  [i][h][k]
__device__ float  g_partials[(size_t)BATCH * DH * HID];   // 8.5 MB   [b][i][h]

// ---- helpers ---------------------------------------------------------------
static __device__ __forceinline__ uint32_t smem_u32(const void* p) {
    uint32_t a;
    asm("{ .reg .u64 t; cvta.to.shared.u64 t, %1; cvt.u32.u64 %0, t; }"
        : "=r"(a) : "l"(p));
    return a;
}
static __device__ __forceinline__ void cp16(uint32_t dst, const void* src) {
    asm volatile("cp.async.cg.shared.global [%0], [%1], 16;" :: "r"(dst), "l"(src));
}
#define CP_COMMIT() asm volatile("cp.async.commit_group;" ::: "memory")
#define CP_WAIT1()  asm volatile("cp.async.wait_group 1;" ::: "memory")

static __device__ __forceinline__ void ldm_x4(uint32_t* r, uint32_t addr) {
    asm volatile("ldmatrix.sync.aligned.m8n8.x4.shared.b16 {%0,%1,%2,%3}, [%4];"
                 : "=r"(r[0]), "=r"(r[1]), "=r"(r[2]), "=r"(r[3]) : "r"(addr));
}
static __device__ __forceinline__ void mma16816(float* c, const uint32_t* a,
                                                const uint32_t* b) {
    asm volatile(
        "mma.sync.aligned.m16n8k16.row.col.f32.f16.f16.f32 "
        "{%0,%1,%2,%3}, {%4,%5,%6,%7}, {%8,%9}, {%0,%1,%2,%3};"
        : "+f"(c[0]), "+f"(c[1]), "+f"(c[2]), "+f"(c[3])
        : "r"(a[0]), "r"(a[1]), "r"(a[2]), "r"(a[3]), "r"(b[0]), "r"(b[1]));
}

// ============================================================================
// Kernel A: convert+transpose W1 -> Bp[i][h][k] f16, zero-padded to KPAD.
// ============================================================================
__global__ void convert_w1_kernel(const float* __restrict__ W1) {
    __shared__ float ts[64][65];
    const int c = blockIdx.x, i = blockIdx.y;
    const int tid = threadIdx.x;
    for (int e = tid; e < 4096; e += 256) {
        int kl = e >> 6, h = e & 63;
        int jk = c * 64 + kl;
        ts[kl][h] = (jk < KREAL) ? W1[((size_t)i * KREAL + jk) * HID + h] : 0.0f;
    }
    __syncthreads();
    for (int t = tid; t < 512; t += 256) {
        int h = t >> 3, k16 = t & 7;
        uint32_t u[4];
        #pragma unroll
        for (int q = 0; q < 4; ++q) {
            __half2 p = __halves2half2(__float2half_rn(ts[k16 * 8 + 2 * q][h]),
                                       __float2half_rn(ts[k16 * 8 + 2 * q + 1][h]));
            u[q] = *reinterpret_cast<uint32_t*>(&p);
        }
        *reinterpret_cast<uint4*>(&g_Bp[((size_t)i * HID + h) * KPAD + c * 64 + k16 * 8])
            = make_uint4(u[0], u[1], u[2], u[3]);
    }
}

// ============================================================================
// Kernel B: build G[b][jk] = v_h[b,j]*t_h[b,k] f16, zero-padded. grid 512.
// ============================================================================
__global__ void build_g_kernel(const float* __restrict__ l,
                               const float* __restrict__ v) {
    const int b = blockIdx.x;
    const int tid = threadIdx.x;
    __shared__ float vs[DH], tsh[DH];
    if (tid < DH) vs[tid] = (tid == 0) ? 1.0f : v[(size_t)b * DL + tid - 1];
    if (tid >= 128 && tid < 128 + DH)
        tsh[tid - 128] = (tid == 128) ? 1.0f : l[(size_t)b * DL + tid - 129];
    __syncthreads();
    for (int p = tid; p < KPAD / 2; p += 256) {
        int jk0 = 2 * p, jk1 = 2 * p + 1;
        float f0 = (jk0 < KREAL) ? vs[jk0 / DH] * tsh[jk0 % DH] : 0.0f;
        float f1 = (jk1 < KREAL) ? vs[jk1 / DH] * tsh[jk1 % DH] : 0.0f;
        __half2 h2 = __halves2half2(__float2half_rn(f0), __float2half_rn(f1));
        *reinterpret_cast<uint32_t*>(&g_G[(size_t)b * KPAD + jk0])
            = *reinterpret_cast<uint32_t*>(&h2);
    }
}

// ============================================================================
// Kernel C: main GEMM. grid (4 mtiles, 33 i-pairs), 256 thr, 3-stage pipe.
// smem/stage: A[128 rows][64 f16] (16KB) | B[128 n][64 f16] (16KB), swizzle:
//   16B chunk ch (0-7) stored at ch ^ (row & 7).
// Warps: 4m x 2n; warp tile 32m x 64n; acc 2x8 m16n8 frags.
// Mainloop: CP_WAIT(1) -> sync -> issue(c+2) -> compute(c).  One sync/stage.
// ============================================================================
__global__ void __launch_bounds__(256)
fusion_mma_kernel(const float* __restrict__ a) {
    extern __shared__ char smc[];
    const uint32_t smb = smem_u32(smc);
    const int tid = threadIdx.x;
    const int lane = tid & 31;
    const int warp = tid >> 5;
    const int wm = warp & 3;          // 4 m-warps
    const int wn = warp >> 2;         // 2 n-warps
    const int mt = blockIdx.x, g = blockIdx.y;
    const int b0 = mt * 128;
    const int i0 = g * 2;

    auto issue_loads = [&](int c) {
        if (c >= NC) return;
        const uint32_t Ab = smb + (uint32_t)(c % PIPE) * STAGE_BYTES;
        const uint32_t Bb = Ab + 16384u;
        #pragma unroll
        for (int w = 0; w < 4; ++w) {                 // A: 128 rows x 8 chunks
            int idx = tid + w * 256;
            int row = idx >> 3, ch = idx & 7;
            cp16(Ab + (uint32_t)(row * 128 + ((ch ^ (row & 7)) << 4)),
                 &g_G[(size_t)(b0 + row) * KPAD + c * 64 + ch * 8]);
        }
        #pragma unroll
        for (int w = 0; w < 4; ++w) {                 // B: 128 n-rows x 8 chunks
            int idx = tid + w * 256;
            int n = idx >> 3, ch = idx & 7;
            int i = i0 + (n >> 6); if (i > DH - 1) i = DH - 1;
            int h = n & 63;
            cp16(Bb + (uint32_t)(n * 128 + ((ch ^ (n & 7)) << 4)),
                 &g_Bp[((size_t)i * HID + h) * KPAD + c * 64 + ch * 8]);
        }
    };

    float acc[2][8][4];
    #pragma unroll
    for (int mi = 0; mi < 2; ++mi)
        #pragma unroll
        for (int nj = 0; nj < 8; ++nj)
            #pragma unroll
            for (int q = 0; q < 4; ++q) acc[mi][nj][q] = 0.0f;

    issue_loads(0); CP_COMMIT();
    issue_loads(1); CP_COMMIT();

    for (int c = 0; c < NC; ++c) {
        CP_WAIT1();                    // stage c resident (c+1 may be pending)
        __syncthreads();               // visibility + all warps done stage c-1
        issue_loads(c + 2); CP_COMMIT();   // buf (c+2)%3 == (c-1)%3, now free

        const uint32_t Ab = smb + (uint32_t)(c % PIPE) * STAGE_BYTES;
        const uint32_t Bb = Ab + 16384u;

        #pragma unroll
        for (int ks = 0; ks < 4; ++ks) {
            uint32_t af[2][4];
            #pragma unroll
            for (int mi = 0; mi < 2; ++mi) {
                int row = wm * 32 + mi * 16 + (lane & 15);
                int ch = 2 * ks + (lane >> 4);
                ldm_x4(af[mi], Ab + (uint32_t)(row * 128 + ((ch ^ (row & 7)) << 4)));
            }
            uint32_t bf[8][2];
            #pragma unroll
            for (int nb = 0; nb < 4; ++nb) {
                int nrow = wn * 64 + nb * 16 + (lane & 7) + ((lane >> 4) << 3);
                int ch = 2 * ks + ((lane >> 3) & 1);
                uint32_t r[4];
                ldm_x4(r, Bb + (uint32_t)(nrow * 128 + ((ch ^ (nrow & 7)) << 4)));
                bf[2 * nb][0] = r[0]; bf[2 * nb][1] = r[1];
                bf[2 * nb + 1][0] = r[2]; bf[2 * nb + 1][1] = r[3];
            }
            #pragma unroll
            for (int mi = 0; mi < 2; ++mi)
                #pragma unroll
                for (int nj = 0; nj < 8; ++nj)
                    mma16816(acc[mi][nj], af[mi], bf[nj]);
        }
    }

    // ---- writeout: scale by a_h[b, iw], iw uniform per warp ----
    const int iw = i0 + wn;
    if (iw < DH) {
        #pragma unroll
        for (int mi = 0; mi < 2; ++mi) {
            int bA = b0 + wm * 32 + mi * 16 + (lane >> 2);
            int bB = bA + 8;
            float ahA = (iw == 0) ? 1.0f : __ldg(&a[(size_t)bA * DL + iw - 1]);
            float ahB = (iw == 0) ? 1.0f : __ldg(&a[(size_t)bB * DL + iw - 1]);
            #pragma unroll
            for (int nj = 0; nj < 8; ++nj) {
                int h = nj * 8 + (lane & 3) * 2;
                float2 vA = make_float2(acc[mi][nj][0] * ahA, acc[mi][nj][1] * ahA);
                float2 vB = make_float2(acc[mi][nj][2] * ahB, acc[mi][nj][3] * ahB);
                *reinterpret_cast<float2*>(
                    &g_partials[((size_t)bA * DH + iw) * HID + h]) = vA;
                *reinterpret_cast<float2*>(
                    &g_partials[((size_t)bB * DH + iw) * HID + h]) = vB;
            }
        }
    }
}

// ============================================================================
// Kernel D: fused i-reduction + bias/tanh + two 64x64 layers.
// grid 512 (one block per b), 256 threads: (q,h), q=0..3 partial-sums i.
// ============================================================================
__global__ void mlp_epilogue_kernel(const float* __restrict__ b1,
                                    const float* __restrict__ W2,
                                    const float* __restrict__ b2,
                                    const float* __restrict__ W3,
                                    const float* __restrict__ b3,
                                    float* __restrict__ out) {
    const int b = blockIdx.x;
    const int tid = threadIdx.x;
    const int q = tid >> 6;           // 4 i-slices
    const int h = tid & 63;
    __shared__ float sq[4][HID];
    __shared__ float h1s[HID];
    __shared__ float h2s[HID];

    const float* pr = &g_partials[(size_t)b * DH * HID + h];
    float acc = 0.0f;
    for (int i = q; i < DH; i += 4)   // q=0 gets 17 terms, others 16
        acc += pr[(size_t)i * HID];
    sq[q][h] = acc;
    __syncthreads();

    if (tid < HID) {
        float s = sq[0][h] + sq[1][h] + sq[2][h] + sq[3][h];
        h1s[h] = tanhf(s + b1[h]);
    }
    __syncthreads();

    if (tid < HID) {
        float acc2 = b2[h];
        #pragma unroll
        for (int jj = 0; jj < HID; ++jj)
            acc2 = fmaf(h1s[jj], W2[(size_t)jj * HID + h], acc2);
        h2s[h] = tanhf(acc2);
    }
    __syncthreads();

    if (tid < HID) {
        float acc3 = b3[h];
        #pragma unroll
        for (int jj = 0; jj < HID; ++jj)
            acc3 = fmaf(h2s[jj], W3[(size_t)jj * DL + h], acc3);
        out[(size_t)b * DL + h] = tanhf(acc3);
    }
}

// ============================================================================
extern "C" void kernel_launch(void* const* d_in, const int* in_sizes, int n_in,
                              void* d_out, int out_size) {
    const float* l  = (const float*)d_in[0];
    const float* a  = (const float*)d_in[1];
    const float* v  = (const float*)d_in[2];
    const float* W1 = (const float*)d_in[3];
    const float* b1 = (const float*)d_in[4];
    const float* W2 = (const float*)d_in[5];
    const float* b2 = (const float*)d_in[6];
    const float* W3 = (const float*)d_in[7];
    const float* b3 = (const float*)d_in[8];
    float* out = (float*)d_out;

    cudaFuncSetAttribute(fusion_mma_kernel,
                         cudaFuncAttributeMaxDynamicSharedMemorySize, GEMM_SMEM);

    convert_w1_kernel<<<dim3(NC, DH), 256>>>(W1);
    build_g_kernel<<<BATCH, 256>>>(l, v);
    fusion_mma_kernel<<<dim3(4, 33), 256, GEMM_SMEM>>>(a);
    mlp_epilogue_kernel<<<BATCH, 256>>>(b1, W2, b2, W3, b3, out);
}

// round 13
// speedup vs baseline: 1.0754x; 1.0347x over previous
#include <cuda_runtime.h>
#include <cuda_fp16.h>
#include <cstdint>
#include <cstddef>

// ============================================================================
// out1[b,h] = sum_i a_h[b,i] * (G @ W1_i)[b,h],  G[b,jk] = v_h[b,j]*t_h[b,k]
// GEMM via mma.sync.m16n8k16 (f16 in, f32 accum).
// CTA: 128 rows x 128 cols (i-pair), K=4288, 3-stage cp.async pipeline.
// i-pair reduced IN-CTA (smem) -> g_red[b][33][h] (4.3 MB, half traffic).
// Epilogue: fused 33-group reduction + bias/tanh + two 64x64 layers.
// ============================================================================

#define DL 64
#define DH 65
#define HID 64
#define BATCH 512
#define KREAL 4225          // 65*65 per i
#define KPAD 4288           // 67 chunks of 64
#define NC 67
#define NG 33               // i-pair groups
#define PIPE 3
#define STAGE_BYTES 32768   // A 16KB + B 16KB
#define GEMM_SMEM (PIPE * STAGE_BYTES)

__device__ __half g_G[(size_t)BATCH * KPAD];              // 4.4 MB
__device__ __half g_Bp[(size_t)DH * HID * KPAD];          // 35.7 MB  [i][h][k]
__device__ float  g_red[(size_t)BATCH * NG * HID];        // 4.3 MB   [b][g][h]

// ---- helpers ---------------------------------------------------------------
static __device__ __forceinline__ uint32_t smem_u32(const void* p) {
    uint32_t a;
    asm("{ .reg .u64 t; cvta.to.shared.u64 t, %1; cvt.u32.u64 %0, t; }"
        : "=r"(a) : "l"(p));
    return a;
}
static __device__ __forceinline__ void cp16(uint32_t dst, const void* src) {
    asm volatile("cp.async.cg.shared.global [%0], [%1], 16;" :: "r"(dst), "l"(src));
}
#define CP_COMMIT() asm volatile("cp.async.commit_group;" ::: "memory")
#define CP_WAIT1()  asm volatile("cp.async.wait_group 1;" ::: "memory")

static __device__ __forceinline__ void ldm_x4(uint32_t* r, uint32_t addr) {
    asm volatile("ldmatrix.sync.aligned.m8n8.x4.shared.b16 {%0,%1,%2,%3}, [%4];"
                 : "=r"(r[0]), "=r"(r[1]), "=r"(r[2]), "=r"(r[3]) : "r"(addr));
}
static __device__ __forceinline__ void mma16816(float* c, const uint32_t* a,
                                                const uint32_t* b) {
    asm volatile(
        "mma.sync.aligned.m16n8k16.row.col.f32.f16.f16.f32 "
        "{%0,%1,%2,%3}, {%4,%5,%6,%7}, {%8,%9}, {%0,%1,%2,%3};"
        : "+f"(c[0]), "+f"(c[1]), "+f"(c[2]), "+f"(c[3])
        : "r"(a[0]), "r"(a[1]), "r"(a[2]), "r"(a[3]), "r"(b[0]), "r"(b[1]));
}

// ============================================================================
// Kernel A: convert+transpose W1 -> Bp[i][h][k] f16, zero-padded to KPAD.
// ============================================================================
__global__ void convert_w1_kernel(const float* __restrict__ W1) {
    __shared__ float ts[64][65];
    const int c = blockIdx.x, i = blockIdx.y;
    const int tid = threadIdx.x;
    for (int e = tid; e < 4096; e += 256) {
        int kl = e >> 6, h = e & 63;
        int jk = c * 64 + kl;
        ts[kl][h] = (jk < KREAL) ? W1[((size_t)i * KREAL + jk) * HID + h] : 0.0f;
    }
    __syncthreads();
    for (int t = tid; t < 512; t += 256) {
        int h = t >> 3, k16 = t & 7;
        uint32_t u[4];
        #pragma unroll
        for (int q = 0; q < 4; ++q) {
            __half2 p = __halves2half2(__float2half_rn(ts[k16 * 8 + 2 * q][h]),
                                       __float2half_rn(ts[k16 * 8 + 2 * q + 1][h]));
            u[q] = *reinterpret_cast<uint32_t*>(&p);
        }
        *reinterpret_cast<uint4*>(&g_Bp[((size_t)i * HID + h) * KPAD + c * 64 + k16 * 8])
            = make_uint4(u[0], u[1], u[2], u[3]);
    }
}

// ============================================================================
// Kernel B: build G[b][jk] = v_h[b,j]*t_h[b,k] f16, zero-padded. grid 512.
// ============================================================================
__global__ void build_g_kernel(const float* __restrict__ l,
                               const float* __restrict__ v) {
    const int b = blockIdx.x;
    const int tid = threadIdx.x;
    __shared__ float vs[DH], tsh[DH];
    if (tid < DH) vs[tid] = (tid == 0) ? 1.0f : v[(size_t)b * DL + tid - 1];
    if (tid >= 128 && tid < 128 + DH)
        tsh[tid - 128] = (tid == 128) ? 1.0f : l[(size_t)b * DL + tid - 129];
    __syncthreads();
    for (int p = tid; p < KPAD / 2; p += 256) {
        int jk0 = 2 * p, jk1 = 2 * p + 1;
        float f0 = (jk0 < KREAL) ? vs[jk0 / DH] * tsh[jk0 % DH] : 0.0f;
        float f1 = (jk1 < KREAL) ? vs[jk1 / DH] * tsh[jk1 % DH] : 0.0f;
        __half2 h2 = __halves2half2(__float2half_rn(f0), __float2half_rn(f1));
        *reinterpret_cast<uint32_t*>(&g_G[(size_t)b * KPAD + jk0])
            = *reinterpret_cast<uint32_t*>(&h2);
    }
}

// ============================================================================
// Kernel C: main GEMM. grid (4 mtiles, 33 i-pairs), 256 thr, 3-stage pipe.
// Warps: 4m x 2n; warp tile 32m x 64n (wn = i-index within pair).
// Writeout: wn=1 scales by a_h[i1] into smem; wn=0 scales by a_h[i0], adds,
// stores g_red[b][g][h].
// ============================================================================
__global__ void __launch_bounds__(256)
fusion_mma_kernel(const float* __restrict__ a) {
    extern __shared__ char smc[];
    const uint32_t smb = smem_u32(smc);
    const int tid = threadIdx.x;
    const int lane = tid & 31;
    const int warp = tid >> 5;
    const int wm = warp & 3;          // 4 m-warps
    const int wn = warp >> 2;         // 2 n-warps (i within pair)
    const int mt = blockIdx.x, g = blockIdx.y;
    const int b0 = mt * 128;
    const int i0 = g * 2;

    auto issue_loads = [&](int c) {
        if (c >= NC) return;
        const uint32_t Ab = smb + (uint32_t)(c % PIPE) * STAGE_BYTES;
        const uint32_t Bb = Ab + 16384u;
        #pragma unroll
        for (int w = 0; w < 4; ++w) {                 // A: 128 rows x 8 chunks
            int idx = tid + w * 256;
            int row = idx >> 3, ch = idx & 7;
            cp16(Ab + (uint32_t)(row * 128 + ((ch ^ (row & 7)) << 4)),
                 &g_G[(size_t)(b0 + row) * KPAD + c * 64 + ch * 8]);
        }
        #pragma unroll
        for (int w = 0; w < 4; ++w) {                 // B: 128 n-rows x 8 chunks
            int idx = tid + w * 256;
            int n = idx >> 3, ch = idx & 7;
            int i = i0 + (n >> 6); if (i > DH - 1) i = DH - 1;
            int h = n & 63;
            cp16(Bb + (uint32_t)(n * 128 + ((ch ^ (n & 7)) << 4)),
                 &g_Bp[((size_t)i * HID + h) * KPAD + c * 64 + ch * 8]);
        }
    };

    float acc[2][8][4];
    #pragma unroll
    for (int mi = 0; mi < 2; ++mi)
        #pragma unroll
        for (int nj = 0; nj < 8; ++nj)
            #pragma unroll
            for (int q = 0; q < 4; ++q) acc[mi][nj][q] = 0.0f;

    issue_loads(0); CP_COMMIT();
    issue_loads(1); CP_COMMIT();

    for (int c = 0; c < NC; ++c) {
        CP_WAIT1();                    // stage c resident (c+1 may be pending)
        __syncthreads();               // visibility + all warps done stage c-1
        issue_loads(c + 2); CP_COMMIT();   // buf (c+2)%3 == (c-1)%3, now free

        const uint32_t Ab = smb + (uint32_t)(c % PIPE) * STAGE_BYTES;
        const uint32_t Bb = Ab + 16384u;

        #pragma unroll
        for (int ks = 0; ks < 4; ++ks) {
            uint32_t af[2][4];
            #pragma unroll
            for (int mi = 0; mi < 2; ++mi) {
                int row = wm * 32 + mi * 16 + (lane & 15);
                int ch = 2 * ks + (lane >> 4);
                ldm_x4(af[mi], Ab + (uint32_t)(row * 128 + ((ch ^ (row & 7)) << 4)));
            }
            uint32_t bf[8][2];
            #pragma unroll
            for (int nb = 0; nb < 4; ++nb) {
                int nrow = wn * 64 + nb * 16 + (lane & 7) + ((lane >> 4) << 3);
                int ch = 2 * ks + ((lane >> 3) & 1);
                uint32_t r[4];
                ldm_x4(r, Bb + (uint32_t)(nrow * 128 + ((ch ^ (nrow & 7)) << 4)));
                bf[2 * nb][0] = r[0]; bf[2 * nb][1] = r[1];
                bf[2 * nb + 1][0] = r[2]; bf[2 * nb + 1][1] = r[3];
            }
            #pragma unroll
            for (int mi = 0; mi < 2; ++mi)
                #pragma unroll
                for (int nj = 0; nj < 8; ++nj)
                    mma16816(acc[mi][nj], af[mi], bf[nj]);
        }
    }

    // ---- writeout with in-CTA i-pair reduction ----
    // red buffer lives in pipeline buffer 1 (idle: last compute reads buf 0;
    // all still-pending cp.async groups at loop exit are empty).
    float* red = reinterpret_cast<float*>(smc + STAGE_BYTES);   // [128][64]

    if (wn == 1) {
        const int i1 = i0 + 1;
        #pragma unroll
        for (int mi = 0; mi < 2; ++mi) {
            int rA = wm * 32 + mi * 16 + (lane >> 2);
            int rB = rA + 8;
            float ahA = 0.0f, ahB = 0.0f;
            if (i1 < DH) {
                ahA = __ldg(&a[(size_t)(b0 + rA) * DL + i1 - 1]);
                ahB = __ldg(&a[(size_t)(b0 + rB) * DL + i1 - 1]);
            }
            #pragma unroll
            for (int nj = 0; nj < 8; ++nj) {
                int h = nj * 8 + (lane & 3) * 2;
                *reinterpret_cast<float2*>(&red[rA * 64 + h]) =
                    make_float2(acc[mi][nj][0] * ahA, acc[mi][nj][1] * ahA);
                *reinterpret_cast<float2*>(&red[rB * 64 + h]) =
                    make_float2(acc[mi][nj][2] * ahB, acc[mi][nj][3] * ahB);
            }
        }
    }
    __syncthreads();

    if (wn == 0) {
        #pragma unroll
        for (int mi = 0; mi < 2; ++mi) {
            int rA = wm * 32 + mi * 16 + (lane >> 2);
            int rB = rA + 8;
            float ahA = (i0 == 0) ? 1.0f
                                  : __ldg(&a[(size_t)(b0 + rA) * DL + i0 - 1]);
            float ahB = (i0 == 0) ? 1.0f
                                  : __ldg(&a[(size_t)(b0 + rB) * DL + i0 - 1]);
            #pragma unroll
            for (int nj = 0; nj < 8; ++nj) {
                int h = nj * 8 + (lane & 3) * 2;
                float2 pA = *reinterpret_cast<const float2*>(&red[rA * 64 + h]);
                float2 pB = *reinterpret_cast<const float2*>(&red[rB * 64 + h]);
                float2 vA = make_float2(fmaf(acc[mi][nj][0], ahA, pA.x),
                                        fmaf(acc[mi][nj][1], ahA, pA.y));
                float2 vB = make_float2(fmaf(acc[mi][nj][2], ahB, pB.x),
                                        fmaf(acc[mi][nj][3], ahB, pB.y));
                *reinterpret_cast<float2*>(
                    &g_red[((size_t)(b0 + rA) * NG + g) * HID + h]) = vA;
                *reinterpret_cast<float2*>(
                    &g_red[((size_t)(b0 + rB) * NG + g) * HID + h]) = vB;
            }
        }
    }
}

// ============================================================================
// Kernel D: fused 33-group reduction + bias/tanh + two 64x64 layers.
// grid 512 (one block per b), 256 threads: (q,h), q=0..3 slices the g-sum.
// ============================================================================
__global__ void mlp_epilogue_kernel(const float* __restrict__ b1,
                                    const float* __restrict__ W2,
                                    const float* __restrict__ b2,
                                    const float* __restrict__ W3,
                                    const float* __restrict__ b3,
                                    float* __restrict__ out) {
    const int b = blockIdx.x;
    const int tid = threadIdx.x;
    const int q = tid >> 6;           // 4 g-slices
    const int h = tid & 63;
    __shared__ float sq[4][HID];
    __shared__ float h1s[HID];
    __shared__ float h2s[HID];

    const float* pr = &g_red[(size_t)b * NG * HID + h];
    float acc = 0.0f;
    for (int g = q; g < NG; g += 4)   // q=0 gets 9 terms, others 8
        acc += pr[(size_t)g * HID];
    sq[q][h] = acc;
    __syncthreads();

    if (tid < HID) {
        float s = sq[0][h] + sq[1][h] + sq[2][h] + sq[3][h];
        h1s[h] = tanhf(s + b1[h]);
    }
    __syncthreads();

    if (tid < HID) {
        float acc2 = b2[h];
        #pragma unroll
        for (int jj = 0; jj < HID; ++jj)
            acc2 = fmaf(h1s[jj], W2[(size_t)jj * HID + h], acc2);
        h2s[h] = tanhf(acc2);
    }
    __syncthreads();

    if (tid < HID) {
        float acc3 = b3[h];
        #pragma unroll
        for (int jj = 0; jj < HID; ++jj)
            acc3 = fmaf(h2s[jj], W3[(size_t)jj * DL + h], acc3);
        out[(size_t)b * DL + h] = tanhf(acc3);
    }
}

// ============================================================================
extern "C" void kernel_launch(void* const* d_in, const int* in_sizes, int n_in,
                              void* d_out, int out_size) {
    const float* l  = (const float*)d_in[0];
    const float* a  = (const float*)d_in[1];
    const float* v  = (const float*)d_in[2];
    const float* W1 = (const float*)d_in[3];
    const float* b1 = (const float*)d_in[4];
    const float* W2 = (const float*)d_in[5];
    const float* b2 = (const float*)d_in[6];
    const float* W3 = (const float*)d_in[7];
    const float* b3 = (const float*)d_in[8];
    float* out = (float*)d_out;

    cudaFuncSetAttribute(fusion_mma_kernel,
                         cudaFuncAttributeMaxDynamicSharedMemorySize, GEMM_SMEM);

    convert_w1_kernel<<<dim3(NC, DH), 256>>>(W1);
    build_g_kernel<<<BATCH, 256>>>(l, v);
    fusion_mma_kernel<<<dim3(4, NG), 256, GEMM_SMEM>>>(a);
    mlp_epilogue_kernel<<<BATCH, 256>>>(b1, W2, b2, W3, b3, out);
}